// round 14
// baseline (speedup 1.0000x reference)
#include <cuda_runtime.h>
#include <cuda_bf16.h>
#include <cuda_fp16.h>
#include <cstdint>

#define MAXN 50048
#define MAXE 860032
#define IN_DIM 128
#define HEADS 4
#define OUT_DIM 64
#define FTOT 256

// ---------------- scratch ----------------
__device__ unsigned g_hh[(size_t)MAXN * 128];   // h as half2 pairs: 25.6 MB
__device__ float4 g_asrc[MAXN];
__device__ float4 g_adst[MAXN];
__device__ int    g_src[MAXE];
__device__ int    g_cnt[MAXN];
__device__ int    g_off[MAXN + 1];
__device__ int    g_cur[MAXN];
__device__ int    g_bsum[256];
__device__ int    g_boff[256];
__device__ __align__(16) __half g_wt[FTOT * IN_DIM];  // W^T fp16: [n][k]

__device__ __forceinline__ float lrelu(float e) {
    return e > 0.0f ? e : 0.2f * e;
}

__device__ __forceinline__ int edge_stride(const unsigned* w) {
    int is64 = 1;
    #pragma unroll 1
    for (int j = 1; j < 64; j += 2)
        if (w[j] != 0u) { is64 = 0; break; }
    return is64 ? 2 : 1;
}

// ---------------- 1: zero degree counters ----------------
__global__ void zero_cnt_kernel(int N) {
    int i = blockIdx.x * blockDim.x + threadIdx.x;
    if (i < N) g_cnt[i] = 0;
}

// ---------------- 2: histogram (4 edges/thread) ----------------
__global__ void hist_kernel(const unsigned* __restrict__ w, int E, int N) {
    __shared__ int s_st;
    if (threadIdx.x == 0) s_st = edge_stride(w);
    __syncthreads();
    int st = s_st;
    int ET = E + N;
    int base = (blockIdx.x * blockDim.x + threadIdx.x) * 4;
    if (base >= ET) return;
    if (base + 4 <= ET) {
        int d[4];
        #pragma unroll
        for (int q = 0; q < 4; q++) {
            int i = base + q;
            d[q] = (i < E) ? (int)w[st * E + st * i] : (i - E);
        }
        #pragma unroll
        for (int q = 0; q < 4; q++) atomicAdd(&g_cnt[d[q]], 1);
    } else {
        for (int i = base; i < ET; i++) {
            int d = (i < E) ? (int)w[st * E + st * i] : (i - E);
            atomicAdd(&g_cnt[d], 1);
        }
    }
}

// ---------------- 3: W transpose -> fp16 ----------------
__global__ void wt_kernel(const float* __restrict__ W) {
    int i = blockIdx.x * 256 + threadIdx.x;     // 0..32767
    int k = i & 127, n = i >> 7;
    g_wt[i] = __float2half_rn(__ldg(W + (size_t)k * FTOT + n));
}

// ---------------- 4: GEMM on fp16 HMMA, 4 heads/CTA, fused att logits -----
#define PA 136
#define SM_A 0                                   // 34816
#define SM_ATTV 34816                            // 2048 -> 36864
#define SM_B 36864                               // 17408 (B tile)
#define SM_STG 36864                             // 20480 (overlays B)
#define SM_RED 36864                             // 1024 (overlays stg warp0)
#define SMEM_BYTES 57344

__global__ void __launch_bounds__(256, 4)
gemm_kernel(const float* __restrict__ x,
            const float* __restrict__ att_src,
            const float* __restrict__ att_dst, int N) {
    extern __shared__ __align__(16) char sm[];
    __half* As = (__half*)(sm + SM_A);
    __half* Bs = (__half*)(sm + SM_B);
    float* attv  = (float*)(sm + SM_ATTV);       // [512]: src 0..255, dst 256..
    float* red_s = (float*)(sm + SM_RED);        // [128]
    float* red_d = red_s + 128;

    const int tid = threadIdx.x;
    const int lane = tid & 31, wid = tid >> 5;
    const int mw = wid & 3, nw = wid >> 2;
    const int m_base = blockIdx.x * 128;

    if (tid < 256) {
        attv[tid] = __ldg(att_src + tid);
        attv[256 + tid] = __ldg(att_dst + tid);
    }

    const int ar = tid >> 3;
    const int ac = tid & 7;

    // ---- A fill: 128 rows x 128 k -> fp16, coalesced, once ----
    #pragma unroll
    for (int rr = 0; rr < 4; rr++) {
        int r = ar + rr * 32;
        int grow = m_base + r;
        if (grow >= N) grow = N - 1;
        const float4* xs = (const float4*)(x + (size_t)grow * IN_DIM);
        #pragma unroll
        for (int p = 0; p < 4; p++) {
            float4 v = __ldg(xs + ac + p * 8);
            __half2 h0 = __floats2half2_rn(v.x, v.y);
            __half2 h1 = __floats2half2_rn(v.z, v.w);
            uint2 u;
            u.x = *reinterpret_cast<unsigned*>(&h0);
            u.y = *reinterpret_cast<unsigned*>(&h1);
            *(uint2*)(As + r * PA + (ac + p * 8) * 4) = u;
        }
    }

    const int aoff = (mw * 32 + (lane >> 2)) * PA + (lane & 3) * 2;
    const int boff = (nw * 32 + (lane >> 2)) * PA + (lane & 3) * 2;
    unsigned* stg = (unsigned*)(sm + SM_STG) + wid * (32 * 20);

    #pragma unroll 1
    for (int head = 0; head < HEADS; head++) {
        __syncthreads();
        // ---- B fill: 64 n-rows x 128 k for this head ----
        {
            int n = tid >> 2, q = tid & 3;
            const uint4* s = (const uint4*)(g_wt +
                (size_t)(head * OUT_DIM + n) * IN_DIM);
            uint4* dptr = (uint4*)(Bs + n * PA);
            #pragma unroll
            for (int j = 0; j < 4; j++)
                dptr[q * 4 + j] = __ldg(s + q * 4 + j);
        }
        __syncthreads();

        float acc[2][4][4];
        #pragma unroll
        for (int mt = 0; mt < 2; mt++)
            #pragma unroll
            for (int nt = 0; nt < 4; nt++)
                #pragma unroll
                for (int c = 0; c < 4; c++) acc[mt][nt][c] = 0.0f;

        // ---- HMMA over K=128 ----
        #pragma unroll
        for (int kk = 0; kk < 128; kk += 16) {
            unsigned a[2][4], b[4][2];
            #pragma unroll
            for (int mt = 0; mt < 2; mt++) {
                const __half* p = As + aoff + mt * 16 * PA + kk;
                a[mt][0] = *(const unsigned*)(p);
                a[mt][1] = *(const unsigned*)(p + 8 * PA);
                a[mt][2] = *(const unsigned*)(p + 8);
                a[mt][3] = *(const unsigned*)(p + 8 * PA + 8);
            }
            #pragma unroll
            for (int nt = 0; nt < 4; nt++) {
                const __half* p = Bs + boff + nt * 8 * PA + kk;
                b[nt][0] = *(const unsigned*)(p);
                b[nt][1] = *(const unsigned*)(p + 8);
            }
            #pragma unroll
            for (int mt = 0; mt < 2; mt++)
                #pragma unroll
                for (int nt = 0; nt < 4; nt++)
                    asm volatile(
                        "mma.sync.aligned.m16n8k16.row.col.f32.f16.f16.f32 "
                        "{%0,%1,%2,%3}, {%4,%5,%6,%7}, {%8,%9}, {%0,%1,%2,%3};"
                        : "+f"(acc[mt][nt][0]), "+f"(acc[mt][nt][1]),
                          "+f"(acc[mt][nt][2]), "+f"(acc[mt][nt][3])
                        : "r"(a[mt][0]), "r"(a[mt][1]), "r"(a[mt][2]), "r"(a[mt][3]),
                          "r"(b[nt][0]), "r"(b[nt][1]));
        }

        __syncthreads();

        // ---- h staging (overlays Bs) -> coalesced g_hh stores ----
        #pragma unroll
        for (int mt = 0; mt < 2; mt++)
            #pragma unroll
            for (int nt = 0; nt < 4; nt++) {
                int rl = mt * 16 + (lane >> 2);
                int cu = nt * 4 + (lane & 3);
                __half2 lo = __floats2half2_rn(acc[mt][nt][0], acc[mt][nt][1]);
                __half2 hi = __floats2half2_rn(acc[mt][nt][2], acc[mt][nt][3]);
                stg[rl * 20 + cu] = *reinterpret_cast<unsigned*>(&lo);
                stg[(rl + 8) * 20 + cu] = *reinterpret_cast<unsigned*>(&hi);
            }
        __syncwarp();
        #pragma unroll
        for (int it = 0; it < 4; it++) {
            int rl = it * 8 + (lane >> 2);
            uint4 v = *(uint4*)(stg + rl * 20 + (lane & 3) * 4);
            int grow = m_base + mw * 32 + rl;
            *(uint4*)(g_hh + (size_t)grow * 128 + head * 32 + nw * 16 +
                      (lane & 3) * 4) = v;
        }

        // ---- att logits from fp32 acc ----
        float s1v[2][2], s2v[2][2];
        #pragma unroll
        for (int mt = 0; mt < 2; mt++)
            #pragma unroll
            for (int half = 0; half < 2; half++) {
                float t1 = 0.f, t2 = 0.f;
                #pragma unroll
                for (int nt = 0; nt < 4; nt++)
                    #pragma unroll
                    for (int c2 = 0; c2 < 2; c2++) {
                        int col = head * 64 + nw * 32 + nt * 8 +
                                  (lane & 3) * 2 + c2;
                        float v = acc[mt][nt][half * 2 + c2];
                        t1 = fmaf(v, attv[col], t1);
                        t2 = fmaf(v, attv[256 + col], t2);
                    }
                t1 += __shfl_xor_sync(0xffffffffu, t1, 1);
                t1 += __shfl_xor_sync(0xffffffffu, t1, 2);
                t2 += __shfl_xor_sync(0xffffffffu, t2, 1);
                t2 += __shfl_xor_sync(0xffffffffu, t2, 2);
                s1v[mt][half] = t1;
                s2v[mt][half] = t2;
            }
        __syncthreads();
        if (nw == 0 && (lane & 3) == 0) {
            #pragma unroll
            for (int mt = 0; mt < 2; mt++)
                #pragma unroll
                for (int half = 0; half < 2; half++) {
                    int rl = mw * 32 + mt * 16 + half * 8 + (lane >> 2);
                    red_s[rl] = s1v[mt][half];
                    red_d[rl] = s2v[mt][half];
                }
        }
        __syncthreads();
        if (nw == 1 && (lane & 3) == 0) {
            #pragma unroll
            for (int mt = 0; mt < 2; mt++)
                #pragma unroll
                for (int half = 0; half < 2; half++) {
                    int rl = mw * 32 + mt * 16 + half * 8 + (lane >> 2);
                    int row = m_base + rl;
                    if (row < N) {
                        ((float*)&g_asrc[row])[head] = s1v[mt][half] + red_s[rl];
                        ((float*)&g_adst[row])[head] = s2v[mt][half] + red_d[rl];
                    }
                }
        }
    }
}

// ---------------- 5: three-phase exclusive scan ----------------
__global__ void scan_a_kernel(int N) {
    __shared__ int sh[256];
    int idx = blockIdx.x * 256 + threadIdx.x;
    int v = (idx < N) ? g_cnt[idx] : 0;
    sh[threadIdx.x] = v;
    __syncthreads();
    #pragma unroll
    for (int off = 128; off >= 1; off >>= 1) {
        if (threadIdx.x < off) sh[threadIdx.x] += sh[threadIdx.x + off];
        __syncthreads();
    }
    if (threadIdx.x == 0) g_bsum[blockIdx.x] = sh[0];
}

__global__ void scan_b_kernel(int GB) {
    __shared__ int sh[256];
    int t = threadIdx.x;
    int v = (t < GB) ? g_bsum[t] : 0;
    sh[t] = v;
    __syncthreads();
    #pragma unroll
    for (int off = 1; off < 256; off <<= 1) {
        int u = (t >= off) ? sh[t - off] : 0;
        __syncthreads();
        sh[t] += u;
        __syncthreads();
    }
    g_boff[t] = sh[t] - v;
}

__global__ void scan_c_kernel(int N, int ET) {
    __shared__ int sh[256];
    int t = threadIdx.x;
    int idx = blockIdx.x * 256 + t;
    int c = (idx < N) ? g_cnt[idx] : 0;
    sh[t] = c;
    __syncthreads();
    #pragma unroll
    for (int off = 1; off < 256; off <<= 1) {
        int u = (t >= off) ? sh[t - off] : 0;
        __syncthreads();
        sh[t] += u;
        __syncthreads();
    }
    int ex = g_boff[blockIdx.x] + sh[t] - c;
    if (idx < N) {
        g_off[idx] = ex;
        g_cur[idx] = ex;
        if (idx == N - 1) g_off[N] = ET;
    }
}

// ---------------- 6: scatter (CSR fill, 4 edges/thread) ----------------
__global__ void scatter_kernel(const unsigned* __restrict__ w, int E, int N) {
    __shared__ int s_st;
    if (threadIdx.x == 0) s_st = edge_stride(w);
    __syncthreads();
    int st = s_st;
    int ET = E + N;
    int base = (blockIdx.x * blockDim.x + threadIdx.x) * 4;
    if (base >= ET) return;
    if (base + 4 <= ET) {
        int s[4], d[4];
        #pragma unroll
        for (int q = 0; q < 4; q++) {
            int i = base + q;
            if (i < E) {
                s[q] = (int)w[st * i];
                d[q] = (int)w[st * E + st * i];
            } else {
                s[q] = d[q] = i - E;
            }
        }
        #pragma unroll
        for (int q = 0; q < 4; q++) {
            int pos = atomicAdd(&g_cur[d[q]], 1);
            g_src[pos] = s[q];
        }
    } else {
        for (int i = base; i < ET; i++) {
            int s, d;
            if (i < E) {
                s = (int)w[st * i];
                d = (int)w[st * E + st * i];
            } else {
                s = d = i - E;
            }
            int pos = atomicAdd(&g_cur[d], 1);
            g_src[pos] = s;
        }
    }
}

// ---------------- 7: fused softmax + aggregate + bias + mix-ELU ------------
// TWO warps per node: warp = (node, half); each warp owns 128 contiguous
// features (heads 2*half, 2*half+1). Lane owns 4 features (one uint2 load).
__device__ __forceinline__ float mixelu(float z) {
    float e = z > 0.0f ? z : expm1f(z);
    return 0.5f * z + 0.5f * e;
}

__global__ void __launch_bounds__(256)
agg_kernel(float* __restrict__ out, const float* __restrict__ bias, int N) {
    int gw = (blockIdx.x * blockDim.x + threadIdx.x) >> 5;
    int lane = threadIdx.x & 31;
    int d = gw >> 1;
    int half = gw & 1;
    if (d >= N) return;
    int beg = g_off[d], end = g_off[d + 1];
    bool hsel = (lane & 16) != 0;                // head within the half

    float4 ad4 = g_adst[d];
    float ad = half ? (hsel ? ad4.w : ad4.z) : (hsel ? ad4.y : ad4.x);

    float acc[4] = {0.f, 0.f, 0.f, 0.f};
    float se = 0.f;

    const unsigned* hbase = g_hh + half * 64 + lane * 2;
    #pragma unroll 2
    for (int j = beg; j < end; j++) {
        int s = __ldcs(&g_src[j]);
        float4 as4 = __ldg(&g_asrc[s]);
        float as = half ? (hsel ? as4.w : as4.z) : (hsel ? as4.y : as4.x);
        float e = __expf(lrelu(as + ad));
        se += e;
        uint2 u = __ldg((const uint2*)(hbase + (size_t)s * 128));
        float2 p0 = __half22float2(*reinterpret_cast<__half2*>(&u.x));
        float2 p1 = __half22float2(*reinterpret_cast<__half2*>(&u.y));
        acc[0] = fmaf(e, p0.x, acc[0]); acc[1] = fmaf(e, p0.y, acc[1]);
        acc[2] = fmaf(e, p1.x, acc[2]); acc[3] = fmaf(e, p1.y, acc[3]);
    }

    float inv = 1.0f / (se + 1e-16f);
    const float* brow = bias + half * 128 + lane * 4;
    float4 o;
    o.x = mixelu(acc[0] * inv + __ldg(brow + 0));
    o.y = mixelu(acc[1] * inv + __ldg(brow + 1));
    o.z = mixelu(acc[2] * inv + __ldg(brow + 2));
    o.w = mixelu(acc[3] * inv + __ldg(brow + 3));

    __stcs((float4*)(out + (size_t)d * FTOT + half * 128) + lane, o);
}

// ---------------- launch: fork-join across two side streams ----------------
extern "C" void kernel_launch(void* const* d_in, const int* in_sizes, int n_in,
                              void* d_out, int out_size) {
    const float*    x       = (const float*)d_in[0];
    const unsigned* edge    = (const unsigned*)d_in[1];
    const float*    W       = (const float*)d_in[2];
    const float*    att_src = (const float*)d_in[3];
    const float*    att_dst = (const float*)d_in[4];
    const float*    bias    = (const float*)d_in[5];
    float*          out     = (float*)d_out;

    const int N = in_sizes[0] / IN_DIM;        // 50000
    const int E = in_sizes[1] / 2;             // 800000
    const int ET = E + N;
    const int GB = (N + 255) / 256;

    static cudaStream_t s1 = nullptr, s2 = nullptr;
    static cudaEvent_t e0 = nullptr, e1 = nullptr, e2 = nullptr;
    if (s1 == nullptr) {
        cudaStreamCreateWithFlags(&s1, cudaStreamNonBlocking);
        cudaStreamCreateWithFlags(&s2, cudaStreamNonBlocking);
        cudaEventCreateWithFlags(&e0, cudaEventDisableTiming);
        cudaEventCreateWithFlags(&e1, cudaEventDisableTiming);
        cudaEventCreateWithFlags(&e2, cudaEventDisableTiming);
        cudaFuncSetAttribute(gemm_kernel,
                             cudaFuncAttributeMaxDynamicSharedMemorySize,
                             SMEM_BYTES);
    }

    // fork from the capture-origin (default) stream
    cudaEventRecord(e0, 0);
    cudaStreamWaitEvent(s1, e0, 0);
    cudaStreamWaitEvent(s2, e0, 0);

    // branch 1: feature pipeline (x, W)
    wt_kernel<<<128, 256, 0, s1>>>(W);
    gemm_kernel<<<(N + 127) / 128, 256, SMEM_BYTES, s1>>>(x, att_src, att_dst, N);
    cudaEventRecord(e1, s1);

    // branch 2: edge/CSR pipeline
    zero_cnt_kernel<<<(N + 255) / 256, 256, 0, s2>>>(N);
    hist_kernel<<<(ET + 1023) / 1024, 256, 0, s2>>>(edge, E, N);
    scan_a_kernel<<<GB, 256, 0, s2>>>(N);
    scan_b_kernel<<<1, 256, 0, s2>>>(GB);
    scan_c_kernel<<<GB, 256, 0, s2>>>(N, ET);
    scatter_kernel<<<(ET + 1023) / 1024, 256, 0, s2>>>(edge, E, N);
    cudaEventRecord(e2, s2);

    // join on the origin stream, then aggregate (2 warps per node)
    cudaStreamWaitEvent(0, e1, 0);
    cudaStreamWaitEvent(0, e2, 0);
    agg_kernel<<<((long)N * 64 + 255) / 256, 256>>>(out, bias, N);
}

// round 15
// speedup vs baseline: 1.2116x; 1.2116x over previous
#include <cuda_runtime.h>
#include <cuda_bf16.h>
#include <cuda_fp16.h>
#include <cstdint>

#define MAXN 50048
#define MAXE 860032
#define IN_DIM 128
#define HEADS 4
#define OUT_DIM 64
#define FTOT 256

// ---------------- scratch ----------------
__device__ unsigned g_hh[(size_t)MAXN * 128];   // h as half2 pairs: 25.6 MB
__device__ float4 g_asrc[MAXN];
__device__ float4 g_adst[MAXN];
__device__ int    g_src[MAXE];
__device__ int    g_cnt[MAXN];
__device__ int    g_off[MAXN + 1];
__device__ int    g_cur[MAXN];
__device__ int    g_bsum[256];
__device__ __align__(16) __half g_wt[FTOT * IN_DIM];  // W^T fp16: [n][k]

__device__ __forceinline__ float lrelu(float e) {
    return e > 0.0f ? e : 0.2f * e;
}

__device__ __forceinline__ int edge_stride(const unsigned* w) {
    int is64 = 1;
    #pragma unroll 1
    for (int j = 1; j < 64; j += 2)
        if (w[j] != 0u) { is64 = 0; break; }
    return is64 ? 2 : 1;
}

// ---------------- 1: prep — zero degree counters + W transpose ------------
__global__ void prep_kernel(const float* __restrict__ W, int N) {
    int i = blockIdx.x * blockDim.x + threadIdx.x;
    if (i < N) g_cnt[i] = 0;
    if (i < FTOT * IN_DIM) {
        int k = i & 127, n = i >> 7;
        g_wt[i] = __float2half_rn(__ldg(W + (size_t)k * FTOT + n));
    }
}

// ---------------- 2: histogram (4 edges/thread) ----------------
__global__ void hist_kernel(const unsigned* __restrict__ w, int E, int N) {
    __shared__ int s_st;
    if (threadIdx.x == 0) s_st = edge_stride(w);
    __syncthreads();
    int st = s_st;
    int ET = E + N;
    int base = (blockIdx.x * blockDim.x + threadIdx.x) * 4;
    if (base >= ET) return;
    if (base + 4 <= ET) {
        int d[4];
        #pragma unroll
        for (int q = 0; q < 4; q++) {
            int i = base + q;
            d[q] = (i < E) ? (int)w[st * E + st * i] : (i - E);
        }
        #pragma unroll
        for (int q = 0; q < 4; q++) atomicAdd(&g_cnt[d[q]], 1);
    } else {
        for (int i = base; i < ET; i++) {
            int d = (i < E) ? (int)w[st * E + st * i] : (i - E);
            atomicAdd(&g_cnt[d], 1);
        }
    }
}

// ---------------- 3: GEMM on fp16 HMMA, 4 heads/CTA, fused att logits -----
#define PA 136
#define SM_A 0                                   // 34816
#define SM_ATTV 34816                            // 2048 -> 36864
#define SM_B 36864                               // 17408 (B tile)
#define SM_STG 36864                             // 20480 (overlays B)
#define SM_RED 36864                             // 1024 (overlays stg warp0)
#define SMEM_BYTES 57344

__global__ void __launch_bounds__(256, 4)
gemm_kernel(const float* __restrict__ x,
            const float* __restrict__ att_src,
            const float* __restrict__ att_dst, int N) {
    extern __shared__ __align__(16) char sm[];
    __half* As = (__half*)(sm + SM_A);
    __half* Bs = (__half*)(sm + SM_B);
    float* attv  = (float*)(sm + SM_ATTV);       // [512]: src 0..255, dst 256..
    float* red_s = (float*)(sm + SM_RED);        // [128]
    float* red_d = red_s + 128;

    const int tid = threadIdx.x;
    const int lane = tid & 31, wid = tid >> 5;
    const int mw = wid & 3, nw = wid >> 2;
    const int m_base = blockIdx.x * 128;

    if (tid < 256) {
        attv[tid] = __ldg(att_src + tid);
        attv[256 + tid] = __ldg(att_dst + tid);
    }

    const int ar = tid >> 3;
    const int ac = tid & 7;

    // ---- A fill: 128 rows x 128 k -> fp16, coalesced, once ----
    #pragma unroll
    for (int rr = 0; rr < 4; rr++) {
        int r = ar + rr * 32;
        int grow = m_base + r;
        if (grow >= N) grow = N - 1;
        const float4* xs = (const float4*)(x + (size_t)grow * IN_DIM);
        #pragma unroll
        for (int p = 0; p < 4; p++) {
            float4 v = __ldg(xs + ac + p * 8);
            __half2 h0 = __floats2half2_rn(v.x, v.y);
            __half2 h1 = __floats2half2_rn(v.z, v.w);
            uint2 u;
            u.x = *reinterpret_cast<unsigned*>(&h0);
            u.y = *reinterpret_cast<unsigned*>(&h1);
            *(uint2*)(As + r * PA + (ac + p * 8) * 4) = u;
        }
    }

    const int aoff = (mw * 32 + (lane >> 2)) * PA + (lane & 3) * 2;
    const int boff = (nw * 32 + (lane >> 2)) * PA + (lane & 3) * 2;
    unsigned* stg = (unsigned*)(sm + SM_STG) + wid * (32 * 20);

    #pragma unroll 1
    for (int head = 0; head < HEADS; head++) {
        __syncthreads();
        // ---- B fill: 64 n-rows x 128 k for this head ----
        {
            int n = tid >> 2, q = tid & 3;
            const uint4* s = (const uint4*)(g_wt +
                (size_t)(head * OUT_DIM + n) * IN_DIM);
            uint4* dptr = (uint4*)(Bs + n * PA);
            #pragma unroll
            for (int j = 0; j < 4; j++)
                dptr[q * 4 + j] = __ldg(s + q * 4 + j);
        }
        __syncthreads();

        float acc[2][4][4];
        #pragma unroll
        for (int mt = 0; mt < 2; mt++)
            #pragma unroll
            for (int nt = 0; nt < 4; nt++)
                #pragma unroll
                for (int c = 0; c < 4; c++) acc[mt][nt][c] = 0.0f;

        // ---- HMMA over K=128 ----
        #pragma unroll
        for (int kk = 0; kk < 128; kk += 16) {
            unsigned a[2][4], b[4][2];
            #pragma unroll
            for (int mt = 0; mt < 2; mt++) {
                const __half* p = As + aoff + mt * 16 * PA + kk;
                a[mt][0] = *(const unsigned*)(p);
                a[mt][1] = *(const unsigned*)(p + 8 * PA);
                a[mt][2] = *(const unsigned*)(p + 8);
                a[mt][3] = *(const unsigned*)(p + 8 * PA + 8);
            }
            #pragma unroll
            for (int nt = 0; nt < 4; nt++) {
                const __half* p = Bs + boff + nt * 8 * PA + kk;
                b[nt][0] = *(const unsigned*)(p);
                b[nt][1] = *(const unsigned*)(p + 8);
            }
            #pragma unroll
            for (int mt = 0; mt < 2; mt++)
                #pragma unroll
                for (int nt = 0; nt < 4; nt++)
                    asm volatile(
                        "mma.sync.aligned.m16n8k16.row.col.f32.f16.f16.f32 "
                        "{%0,%1,%2,%3}, {%4,%5,%6,%7}, {%8,%9}, {%0,%1,%2,%3};"
                        : "+f"(acc[mt][nt][0]), "+f"(acc[mt][nt][1]),
                          "+f"(acc[mt][nt][2]), "+f"(acc[mt][nt][3])
                        : "r"(a[mt][0]), "r"(a[mt][1]), "r"(a[mt][2]), "r"(a[mt][3]),
                          "r"(b[nt][0]), "r"(b[nt][1]));
        }

        __syncthreads();

        // ---- h staging (overlays Bs) -> coalesced g_hh stores ----
        #pragma unroll
        for (int mt = 0; mt < 2; mt++)
            #pragma unroll
            for (int nt = 0; nt < 4; nt++) {
                int rl = mt * 16 + (lane >> 2);
                int cu = nt * 4 + (lane & 3);
                __half2 lo = __floats2half2_rn(acc[mt][nt][0], acc[mt][nt][1]);
                __half2 hi = __floats2half2_rn(acc[mt][nt][2], acc[mt][nt][3]);
                stg[rl * 20 + cu] = *reinterpret_cast<unsigned*>(&lo);
                stg[(rl + 8) * 20 + cu] = *reinterpret_cast<unsigned*>(&hi);
            }
        __syncwarp();
        #pragma unroll
        for (int it = 0; it < 4; it++) {
            int rl = it * 8 + (lane >> 2);
            uint4 v = *(uint4*)(stg + rl * 20 + (lane & 3) * 4);
            int grow = m_base + mw * 32 + rl;
            *(uint4*)(g_hh + (size_t)grow * 128 + head * 32 + nw * 16 +
                      (lane & 3) * 4) = v;
        }

        // ---- att logits from fp32 acc ----
        float s1v[2][2], s2v[2][2];
        #pragma unroll
        for (int mt = 0; mt < 2; mt++)
            #pragma unroll
            for (int half = 0; half < 2; half++) {
                float t1 = 0.f, t2 = 0.f;
                #pragma unroll
                for (int nt = 0; nt < 4; nt++)
                    #pragma unroll
                    for (int c2 = 0; c2 < 2; c2++) {
                        int col = head * 64 + nw * 32 + nt * 8 +
                                  (lane & 3) * 2 + c2;
                        float v = acc[mt][nt][half * 2 + c2];
                        t1 = fmaf(v, attv[col], t1);
                        t2 = fmaf(v, attv[256 + col], t2);
                    }
                t1 += __shfl_xor_sync(0xffffffffu, t1, 1);
                t1 += __shfl_xor_sync(0xffffffffu, t1, 2);
                t2 += __shfl_xor_sync(0xffffffffu, t2, 1);
                t2 += __shfl_xor_sync(0xffffffffu, t2, 2);
                s1v[mt][half] = t1;
                s2v[mt][half] = t2;
            }
        __syncthreads();
        if (nw == 0 && (lane & 3) == 0) {
            #pragma unroll
            for (int mt = 0; mt < 2; mt++)
                #pragma unroll
                for (int half = 0; half < 2; half++) {
                    int rl = mw * 32 + mt * 16 + half * 8 + (lane >> 2);
                    red_s[rl] = s1v[mt][half];
                    red_d[rl] = s2v[mt][half];
                }
        }
        __syncthreads();
        if (nw == 1 && (lane & 3) == 0) {
            #pragma unroll
            for (int mt = 0; mt < 2; mt++)
                #pragma unroll
                for (int half = 0; half < 2; half++) {
                    int rl = mw * 32 + mt * 16 + half * 8 + (lane >> 2);
                    int row = m_base + rl;
                    if (row < N) {
                        ((float*)&g_asrc[row])[head] = s1v[mt][half] + red_s[rl];
                        ((float*)&g_adst[row])[head] = s2v[mt][half] + red_d[rl];
                    }
                }
        }
    }
}

// ---------------- 4: scan phase A — per-block sums ----------------
__global__ void scan_a_kernel(int N) {
    __shared__ int sh[256];
    int idx = blockIdx.x * 256 + threadIdx.x;
    int v = (idx < N) ? g_cnt[idx] : 0;
    sh[threadIdx.x] = v;
    __syncthreads();
    #pragma unroll
    for (int off = 128; off >= 1; off >>= 1) {
        if (threadIdx.x < off) sh[threadIdx.x] += sh[threadIdx.x + off];
        __syncthreads();
    }
    if (threadIdx.x == 0) g_bsum[blockIdx.x] = sh[0];
}

// ---------------- 5: scan phase C — block prefix (inline) + local scan ----
__global__ void scan_c_kernel(int N, int ET, int GB) {
    __shared__ int sh[256];
    __shared__ int sh_boff;
    int t = threadIdx.x;

    // inline exclusive prefix of g_bsum over blocks < blockIdx.x
    {
        int v = (t < GB && t < blockIdx.x) ? g_bsum[t] : 0;
        sh[t] = v;
        __syncthreads();
        #pragma unroll
        for (int off = 128; off >= 1; off >>= 1) {
            if (t < off) sh[t] += sh[t + off];
            __syncthreads();
        }
        if (t == 0) sh_boff = sh[0];
        __syncthreads();
    }

    int idx = blockIdx.x * 256 + t;
    int c = (idx < N) ? g_cnt[idx] : 0;
    sh[t] = c;
    __syncthreads();
    #pragma unroll
    for (int off = 1; off < 256; off <<= 1) {
        int u = (t >= off) ? sh[t - off] : 0;
        __syncthreads();
        sh[t] += u;
        __syncthreads();
    }
    int ex = sh_boff + sh[t] - c;
    if (idx < N) {
        g_off[idx] = ex;
        g_cur[idx] = ex;
        if (idx == N - 1) g_off[N] = ET;
    }
}

// ---------------- 6: scatter (CSR fill, 4 edges/thread) ----------------
__global__ void scatter_kernel(const unsigned* __restrict__ w, int E, int N) {
    __shared__ int s_st;
    if (threadIdx.x == 0) s_st = edge_stride(w);
    __syncthreads();
    int st = s_st;
    int ET = E + N;
    int base = (blockIdx.x * blockDim.x + threadIdx.x) * 4;
    if (base >= ET) return;
    if (base + 4 <= ET) {
        int s[4], d[4];
        #pragma unroll
        for (int q = 0; q < 4; q++) {
            int i = base + q;
            if (i < E) {
                s[q] = (int)w[st * i];
                d[q] = (int)w[st * E + st * i];
            } else {
                s[q] = d[q] = i - E;
            }
        }
        #pragma unroll
        for (int q = 0; q < 4; q++) {
            int pos = atomicAdd(&g_cur[d[q]], 1);
            g_src[pos] = s[q];
        }
    } else {
        for (int i = base; i < ET; i++) {
            int s, d;
            if (i < E) {
                s = (int)w[st * i];
                d = (int)w[st * E + st * i];
            } else {
                s = d = i - E;
            }
            int pos = atomicAdd(&g_cur[d], 1);
            g_src[pos] = s;
        }
    }
}

// ---------------- 7: fused softmax + aggregate + bias + mix-ELU ------------
__device__ __forceinline__ float mixelu(float z) {
    float e = z > 0.0f ? z : expm1f(z);
    return 0.5f * z + 0.5f * e;
}

__global__ void __launch_bounds__(256)
agg_kernel(float* __restrict__ out, const float* __restrict__ bias, int N) {
    int gt = blockIdx.x * blockDim.x + threadIdx.x;
    int d = gt >> 5;
    int lane = gt & 31;
    if (d >= N) return;
    int beg = g_off[d], end = g_off[d + 1];
    int head = lane >> 3;
    bool hsel = (head & 1) != 0;
    bool hhi = head >= 2;

    float4 ad4 = g_adst[d];
    float ad = hhi ? (hsel ? ad4.w : ad4.z) : (hsel ? ad4.y : ad4.x);

    float acc[8] = {0.f, 0.f, 0.f, 0.f, 0.f, 0.f, 0.f, 0.f};
    float se = 0.f;

    #pragma unroll 2
    for (int j = beg; j < end; j++) {
        int s = __ldcs(&g_src[j]);
        float4 as4 = __ldg(&g_asrc[s]);
        float as = hhi ? (hsel ? as4.w : as4.z) : (hsel ? as4.y : as4.x);
        float e = __expf(lrelu(as + ad));
        se += e;
        uint4 u = __ldg((const uint4*)(g_hh + (size_t)s * 128) + lane);
        float2 p0 = __half22float2(*reinterpret_cast<__half2*>(&u.x));
        float2 p1 = __half22float2(*reinterpret_cast<__half2*>(&u.y));
        float2 p2 = __half22float2(*reinterpret_cast<__half2*>(&u.z));
        float2 p3 = __half22float2(*reinterpret_cast<__half2*>(&u.w));
        acc[0] = fmaf(e, p0.x, acc[0]); acc[1] = fmaf(e, p0.y, acc[1]);
        acc[2] = fmaf(e, p1.x, acc[2]); acc[3] = fmaf(e, p1.y, acc[3]);
        acc[4] = fmaf(e, p2.x, acc[4]); acc[5] = fmaf(e, p2.y, acc[5]);
        acc[6] = fmaf(e, p3.x, acc[6]); acc[7] = fmaf(e, p3.y, acc[7]);
    }

    float inv = 1.0f / (se + 1e-16f);
    const float* brow = bias + lane * 8;
    float o[8];
    #pragma unroll
    for (int c = 0; c < 8; c++)
        o[c] = mixelu(acc[c] * inv + __ldg(brow + c));

    float4* orow = (float4*)(out + (size_t)d * FTOT);
    __stcs(orow + lane * 2,     make_float4(o[0], o[1], o[2], o[3]));
    __stcs(orow + lane * 2 + 1, make_float4(o[4], o[5], o[6], o[7]));
}

// ---------------- launch: fork-join across two side streams ----------------
extern "C" void kernel_launch(void* const* d_in, const int* in_sizes, int n_in,
                              void* d_out, int out_size) {
    const float*    x       = (const float*)d_in[0];
    const unsigned* edge    = (const unsigned*)d_in[1];
    const float*    W       = (const float*)d_in[2];
    const float*    att_src = (const float*)d_in[3];
    const float*    att_dst = (const float*)d_in[4];
    const float*    bias    = (const float*)d_in[5];
    float*          out     = (float*)d_out;

    const int N = in_sizes[0] / IN_DIM;        // 50000
    const int E = in_sizes[1] / 2;             // 800000
    const int ET = E + N;
    const int GB = (N + 255) / 256;            // 196 <= 256

    static cudaStream_t s1 = nullptr, s2 = nullptr;
    static cudaEvent_t e0 = nullptr, e1 = nullptr, e2 = nullptr;
    if (s1 == nullptr) {
        cudaStreamCreateWithFlags(&s1, cudaStreamNonBlocking);
        cudaStreamCreateWithFlags(&s2, cudaStreamNonBlocking);
        cudaEventCreateWithFlags(&e0, cudaEventDisableTiming);
        cudaEventCreateWithFlags(&e1, cudaEventDisableTiming);
        cudaEventCreateWithFlags(&e2, cudaEventDisableTiming);
        cudaFuncSetAttribute(gemm_kernel,
                             cudaFuncAttributeMaxDynamicSharedMemorySize,
                             SMEM_BYTES);
    }

    // prep (zero counters + W transpose) on the origin stream, then fork
    prep_kernel<<<GB, 256>>>(W, N);
    cudaEventRecord(e0, 0);
    cudaStreamWaitEvent(s1, e0, 0);
    cudaStreamWaitEvent(s2, e0, 0);

    // branch 1: feature pipeline (x, W)
    gemm_kernel<<<(N + 127) / 128, 256, SMEM_BYTES, s1>>>(x, att_src, att_dst, N);
    cudaEventRecord(e1, s1);

    // branch 2: edge/CSR pipeline
    hist_kernel<<<(ET + 1023) / 1024, 256, 0, s2>>>(edge, E, N);
    scan_a_kernel<<<GB, 256, 0, s2>>>(N);
    scan_c_kernel<<<GB, 256, 0, s2>>>(N, ET, GB);
    scatter_kernel<<<(ET + 1023) / 1024, 256, 0, s2>>>(edge, E, N);
    cudaEventRecord(e2, s2);

    // join on the origin stream, then aggregate
    cudaStreamWaitEvent(0, e1, 0);
    cudaStreamWaitEvent(0, e2, 0);
    agg_kernel<<<((long)N * 32 + 255) / 256, 256>>>(out, bias, N);
}